// round 9
// baseline (speedup 1.0000x reference)
#include <cuda_runtime.h>
#include <cstdint>
#include <math.h>

// poses: (4096, 3, 128, 17) float32, channel 1 used.
// out:   [ma(7,4096); mi(7,4096)] stored as float32.
//
// Layout trick: warp w handles batch b; lane L handles frames 4L..4L+3, which
// occupy the CONTIGUOUS float range [68L, 68L+68) of the channel-1 slice.
// 68 floats = 17 float4 (272 B, 16B-aligned) -> 17 independent LDG.128 per
// lane, no shared memory at all.

#define NB 4096
#define FRAMES 128
#define JOINTS 17
#define ROW_F (FRAMES * JOINTS)   // 2176 floats per (batch, channel)
#define WPB 4                     // warps per block = batches per block

// Monotone bijection float <-> signed int (order-preserving for non-NaN).
__device__ __forceinline__ int f2o(float f) {
    int b = __float_as_int(f);
    return b ^ ((b >> 31) & 0x7fffffff);
}
__device__ __forceinline__ float o2f(int k) {
    return __int_as_float(k ^ ((k >> 31) & 0x7fffffff));
}
__device__ __forceinline__ float warp_max_f32(float v) {
    return o2f(__reduce_max_sync(0xffffffffu, f2o(v)));
}
__device__ __forceinline__ float warp_min_f32(float v) {
    return o2f(__reduce_min_sync(0xffffffffu, f2o(v)));
}

__global__ __launch_bounds__(32 * WPB) void divid_part_kernel(
    const float* __restrict__ poses, float* __restrict__ out)
{
    const int lane = threadIdx.x & 31;
    const int w    = threadIdx.x >> 5;
    const int b    = blockIdx.x * WPB + w;

    // ---- 17 independent vector loads: this lane's 4 frames (68 contiguous floats).
    const float4* g4 = reinterpret_cast<const float4*>(
        poses + ((size_t)b * 3 + 1) * ROW_F + lane * 68);
    float4 q[17];
    #pragma unroll
    for (int i = 0; i < 17; i++) q[i] = __ldg(g4 + i);
    const float* qf = reinterpret_cast<const float*>(q);   // static indices only

    float r[14];
    #pragma unroll
    for (int k = 0; k < 7; k++) { r[k] = -INFINITY; r[k + 7] = INFINITY; }

    #pragma unroll
    for (int f = 0; f < 4; f++) {
        float x[JOINTS];
        #pragma unroll
        for (int j = 0; j < JOINTS; j++) x[j] = qf[f * JOINTS + j];  // constant idx

        const float x0 = x[0];
        const float ratio = __fmul_rn(__fadd_rn(__fsub_rn(x[5], x0), __fsub_rn(x[6], x0)), 0.5f);
        const float rcp = __frcp_rn(ratio);

        float v[JOINTS];
        v[0] = 0.0f;                           // (x0 - x0)/ratio == 0 exactly
        #pragma unroll
        for (int j = 1; j < JOINTS; j++)
            v[j] = __fmul_rn(__fsub_rn(x[j], x0), rcp);

        float pmax[7], pmin[7];
        #pragma unroll
        for (int p = 0; p < 7; p++) { pmax[p] = -INFINITY; pmin[p] = INFINITY; }
        #pragma unroll
        for (int j = 0; j < JOINTS; j++) {
            const int p = (j < 5) ? 0 : ((j - 3) >> 1);
            pmax[p] = fmaxf(pmax[p], v[j]);
            pmin[p] = fminf(pmin[p], v[j]);
        }
        float fm = pmin[0];
        #pragma unroll
        for (int p = 1; p < 7; p++) fm = fminf(fm, pmin[p]);
        // max/min commute with the monotone RN-subtraction of fm -> matches reference
        #pragma unroll
        for (int p = 0; p < 7; p++) {
            r[p]     = fmaxf(r[p],     __fsub_rn(pmax[p], fm));
            r[p + 7] = fminf(r[p + 7], __fsub_rn(pmin[p], fm));
        }
    }

    // ---- Warp reduction: 14 integer REDUX ops (result broadcast to all lanes).
    #pragma unroll
    for (int k = 0; k < 7; k++) {
        r[k]     = warp_max_f32(r[k]);
        r[k + 7] = warp_min_f32(r[k + 7]);
    }

    float bottom = r[0], top = r[7];
    #pragma unroll
    for (int p = 1; p < 7; p++) {
        bottom = fmaxf(bottom, r[p]);
        top    = fminf(top,    r[p + 7]);
    }
    const float denom = __fsub_rn(bottom, top);

    // ---- Epilogue (exact IEEE divides, only 14): all lanes compute, lane 0 stores.
    int ma_[7], mi_[7];
    #pragma unroll
    for (int p = 0; p < 7; p++) {
        int ma = (int)ceilf (__fmul_rn(__fdiv_rn(__fsub_rn(r[p],     top), denom), 64.0f));
        int mi = (int)floorf(__fmul_rn(__fdiv_rn(__fsub_rn(r[p + 7], top), denom), 64.0f));
        const int hi = (p + 1) * 9, lo = p * 9;
        if (ma <= mi || ma - mi > 30) { ma = hi; mi = lo; }
        ma_[p] = ma; mi_[p] = mi;
    }
    if (lane == 0) {
        #pragma unroll
        for (int p = 0; p < 7; p++) {
            out[p * NB + b]       = (float)ma_[p];
            out[(7 + p) * NB + b] = (float)mi_[p];
        }
    }
}

extern "C" void kernel_launch(void* const* d_in, const int* in_sizes, int n_in,
                              void* d_out, int out_size)
{
    const float* poses = (const float*)d_in[0];
    float* out = (float*)d_out;
    divid_part_kernel<<<NB / WPB, 32 * WPB>>>(poses, out);
}